// round 2
// baseline (speedup 1.0000x reference)
#include <cuda_runtime.h>
#include <cstdint>
#include <cstddef>

#define B_SZ   8192
#define C_SZ   12
#define DIN    1024
#define DOUT   1024
#define N_COLS (C_SZ * DOUT)   // 12288
#define A_SZ   8

// Scratch (static device allocations are allowed)
__device__ float g_u[(size_t)B_SZ * N_COLS];   // 402 MB
__device__ float g_ent[B_SZ];

// ------------------------------ GEMM ------------------------------
// u[b, co] = sum_i x[b,i] * W[co,i] + bias[co]
// 3xTF32 split-precision: a = hi + lo, acc += hi*hi + hi*lo + lo*hi  (~fp32 accuracy)
#define BM 128
#define BN 128
#define BK 16
#define PK 20   // padded smem row length (floats)

__device__ __forceinline__ void split_tf32(float f, uint32_t& hi, uint32_t& lo) {
    asm("cvt.rna.tf32.f32 %0, %1;" : "=r"(hi) : "f"(f));
    const float lf = f - __uint_as_float(hi);
    asm("cvt.rna.tf32.f32 %0, %1;" : "=r"(lo) : "f"(lf));
}

__device__ __forceinline__ void cp16(void* s, const void* g) {
    uint32_t sa = (uint32_t)__cvta_generic_to_shared(s);
    asm volatile("cp.async.cg.shared.global [%0], [%1], 16;\n" :: "r"(sa), "l"(g));
}

__device__ __forceinline__ void mma_tf32(float acc[4], const uint32_t a[4], const uint32_t b[2]) {
    asm volatile(
        "mma.sync.aligned.m16n8k8.row.col.f32.tf32.tf32.f32 "
        "{%0,%1,%2,%3}, {%4,%5,%6,%7}, {%8,%9}, {%0,%1,%2,%3};\n"
        : "+f"(acc[0]), "+f"(acc[1]), "+f"(acc[2]), "+f"(acc[3])
        : "r"(a[0]), "r"(a[1]), "r"(a[2]), "r"(a[3]), "r"(b[0]), "r"(b[1]));
}

__global__ void __launch_bounds__(256, 2)
gemm_kernel(const float* __restrict__ X, const float* __restrict__ W,
            const float* __restrict__ bias)
{
    __shared__ float sA[2][BM][PK];
    __shared__ float sB[2][BN][PK];

    const int bm = blockIdx.y * BM;
    const int bn = blockIdx.x * BN;
    const int tid  = threadIdx.x;
    const int lane = tid & 31;
    const int warp = tid >> 5;
    const int wm = warp >> 2;   // 0..1  (M dim, 64 rows each)
    const int wn = warp & 3;    // 0..3  (N dim, 32 cols each)

    const int lrow = tid >> 2;        // 0..63
    const int lcol = (tid & 3) * 4;   // 0,4,8,12

    float acc[4][4][4];
    #pragma unroll
    for (int i = 0; i < 4; i++)
        #pragma unroll
        for (int j = 0; j < 4; j++)
            #pragma unroll
            for (int r = 0; r < 4; r++) acc[i][j][r] = 0.f;

    const float* gA = X + (size_t)(bm + lrow) * DIN + lcol;
    const float* gB = W + (size_t)(bn + lrow) * DIN + lcol;

    #pragma unroll
    for (int p = 0; p < 2; p++) {
        cp16(&sA[0][lrow + 64 * p][lcol], gA + (size_t)64 * p * DIN);
        cp16(&sB[0][lrow + 64 * p][lcol], gB + (size_t)64 * p * DIN);
    }
    asm volatile("cp.async.commit_group;\n");

    const int NT = DIN / BK;   // 64
    int buf = 0;
    for (int kt = 0; kt < NT; ++kt) {
        asm volatile("cp.async.wait_group 0;\n");
        __syncthreads();
        if (kt + 1 < NT) {
            const int ko = (kt + 1) * BK;
            #pragma unroll
            for (int p = 0; p < 2; p++) {
                cp16(&sA[buf ^ 1][lrow + 64 * p][lcol], gA + (size_t)64 * p * DIN + ko);
                cp16(&sB[buf ^ 1][lrow + 64 * p][lcol], gB + (size_t)64 * p * DIN + ko);
            }
            asm volatile("cp.async.commit_group;\n");
        }
        #pragma unroll
        for (int ks = 0; ks < 2; ++ks) {
            // load + split A fragments (hi/lo)
            uint32_t ah[4][4], al[4][4];
            const int ar = wm * 64 + (lane >> 2);
            const int ak = ks * 8 + (lane & 3);
            #pragma unroll
            for (int mi = 0; mi < 4; mi++) {
                const int r0 = ar + mi * 16;
                split_tf32(sA[buf][r0    ][ak    ], ah[mi][0], al[mi][0]);
                split_tf32(sA[buf][r0 + 8][ak    ], ah[mi][1], al[mi][1]);
                split_tf32(sA[buf][r0    ][ak + 4], ah[mi][2], al[mi][2]);
                split_tf32(sA[buf][r0 + 8][ak + 4], ah[mi][3], al[mi][3]);
            }
            const int bc = wn * 32 + (lane >> 2);
            #pragma unroll
            for (int ni = 0; ni < 4; ni++) {
                const int n0 = bc + ni * 8;
                uint32_t bh[2], bl[2];
                split_tf32(sB[buf][n0][ak    ], bh[0], bl[0]);
                split_tf32(sB[buf][n0][ak + 4], bh[1], bl[1]);
                #pragma unroll
                for (int mi = 0; mi < 4; mi++) {
                    mma_tf32(acc[mi][ni], al[mi], bh);   // lo*hi (small terms first)
                    mma_tf32(acc[mi][ni], ah[mi], bl);   // hi*lo
                    mma_tf32(acc[mi][ni], ah[mi], bh);   // hi*hi
                }
            }
        }
        buf ^= 1;
    }

    // epilogue: + bias, write to scratch
    #pragma unroll
    for (int mi = 0; mi < 4; mi++) {
        const int row0 = bm + wm * 64 + mi * 16 + (lane >> 2);
        #pragma unroll
        for (int ni = 0; ni < 4; ni++) {
            const int col = bn + wn * 32 + ni * 8 + (lane & 3) * 2;
            const float b0 = bias[col], b1 = bias[col + 1];
            float* o1 = g_u + (size_t)row0 * N_COLS + col;
            float* o2 = g_u + (size_t)(row0 + 8) * N_COLS + col;
            o1[0] = acc[mi][ni][0] + b0;
            o1[1] = acc[mi][ni][1] + b1;
            o2[0] = acc[mi][ni][2] + b0;
            o2[1] = acc[mi][ni][3] + b1;
        }
    }
}

// ------------------------------ Routing ------------------------------
__device__ __forceinline__ float warp_sum(float v) {
    #pragma unroll
    for (int o = 16; o; o >>= 1) v += __shfl_xor_sync(0xffffffffu, v, o);
    return v;
}
__device__ __forceinline__ float warp_max(float v) {
    #pragma unroll
    for (int o = 16; o; o >>= 1) v = fmaxf(v, __shfl_xor_sync(0xffffffffu, v, o));
    return v;
}

__device__ __forceinline__ float block_sum(float v, float* red, int lane, int warp) {
    v = warp_sum(v);
    __syncthreads();
    if (lane == 0) red[warp] = v;
    __syncthreads();
    float t = 0.f;
    #pragma unroll
    for (int w = 0; w < 8; w++) t += red[w];
    return t;
}
__device__ __forceinline__ float block_max(float v, float* red, int lane, int warp) {
    v = warp_max(v);
    __syncthreads();
    if (lane == 0) red[warp] = v;
    __syncthreads();
    float t = -3.0e38f;
    #pragma unroll
    for (int w = 0; w < 8; w++) t = fmaxf(t, red[w]);
    return t;
}

// One CTA per batch row b. Routing is identical across the A=8 axis
// (u_e is an A-broadcast and b starts at 0): compute once, replicate output 8x.
__global__ void __launch_bounds__(256)
routing_kernel(float* __restrict__ out)
{
    const int b = blockIdx.x;
    const int tid = threadIdx.x;
    const int lane = tid & 31, warp = tid >> 5;
    __shared__ float red[8];
    __shared__ float redc[8][12];

    float u[12][4];
    const float* up = g_u + (size_t)b * N_COLS;
    #pragma unroll
    for (int c = 0; c < 12; c++)
        #pragma unroll
        for (int j = 0; j < 4; j++)
            u[c][j] = up[c * 1024 + tid + 256 * j];

    float blog[12];
    #pragma unroll
    for (int c = 0; c < 12; c++) blog[c] = 0.f;

    float s[4];
    float scale = 0.f;

    #pragma unroll
    for (int it = 0; it < 3; ++it) {
        float mx = blog[0];
        #pragma unroll
        for (int c = 1; c < 12; c++) mx = fmaxf(mx, blog[c]);
        float e[12], se = 0.f;
        #pragma unroll
        for (int c = 0; c < 12; c++) { e[c] = __expf(blog[c] - mx); se += e[c]; }
        const float inv = 1.f / se;

        #pragma unroll
        for (int j = 0; j < 4; j++) {
            float t = 0.f;
            #pragma unroll
            for (int c = 0; c < 12; c++) t += e[c] * u[c][j];
            s[j] = t * inv;
        }

        float n2p = s[0]*s[0] + s[1]*s[1] + s[2]*s[2] + s[3]*s[3];
        const float n2 = block_sum(n2p, red, lane, warp);
        const float n = sqrtf(n2);
        scale = n2 / ((1.f + n2) * (n + 1e-8f));

        if (it < 2) {
            float pd[12];
            #pragma unroll
            for (int c = 0; c < 12; c++) {
                float t = u[c][0]*s[0] + u[c][1]*s[1] + u[c][2]*s[2] + u[c][3]*s[3];
                pd[c] = warp_sum(t);
            }
            if (lane == 0) {
                #pragma unroll
                for (int c = 0; c < 12; c++) redc[warp][c] = pd[c];
            }
            __syncthreads();
            #pragma unroll
            for (int c = 0; c < 12; c++) {
                float t = 0.f;
                #pragma unroll
                for (int w = 0; w < 8; w++) t += redc[w][c];
                blog[c] += scale * t;
            }
            __syncthreads();
        }
    }

    float v0[4];
    #pragma unroll
    for (int j = 0; j < 4; j++) v0[j] = scale * s[j];
    const size_t base = (size_t)b * A_SZ * DOUT;
    #pragma unroll
    for (int a = 0; a < A_SZ; a++)
        #pragma unroll
        for (int j = 0; j < 4; j++)
            out[base + (size_t)a * DOUT + tid + 256 * j] = v0[j];

    // entropy over softmax(s) along D_OUT (reference uses pre-squash s)
    float lm = fmaxf(fmaxf(s[0], s[1]), fmaxf(s[2], s[3]));
    const float gm = block_max(lm, red, lane, warp);
    float ex[4], le = 0.f;
    #pragma unroll
    for (int j = 0; j < 4; j++) { ex[j] = __expf(s[j] - gm); le += ex[j]; }
    const float te = block_sum(le, red, lane, warp);
    const float invd = 1.f / (te + 1e-10f);
    float lp = 0.f;
    #pragma unroll
    for (int j = 0; j < 4; j++) {
        const float p = ex[j] * invd;
        lp += p * __logf(p + 1e-10f);
    }
    const float tp = block_sum(lp, red, lane, warp);
    if (tid == 0) {
        float H = -tp;
        H = fminf(fmaxf(H, 0.f), 10.f);
        g_ent[b] = H;
    }
}

// ------------------------------ Finalize ------------------------------
__global__ void __launch_bounds__(256)
finalize_kernel(float* __restrict__ out)
{
    __shared__ float red[8];
    const int tid = threadIdx.x;
    const int lane = tid & 31, warp = tid >> 5;
    float v = 0.f;
    for (int i = tid; i < B_SZ; i += 256) v += g_ent[i];
    const float s = block_sum(v, red, lane, warp);
    if (tid == 0) {
        const float mean = s / (float)B_SZ;   // A axis identical -> mean over B
        const float sig = 1.f / (1.f + expf(-mean));
        out[(size_t)B_SZ * A_SZ * DOUT] = -sig * 0.4f;
    }
}

// ------------------------------ Launch ------------------------------
extern "C" void kernel_launch(void* const* d_in, const int* in_sizes, int n_in,
                              void* d_out, int out_size)
{
    const float* x    = (const float*)d_in[0];   // (8192, 1024)
    const float* W    = (const float*)d_in[1];   // (12, 1024, 1024)
    const float* bias = (const float*)d_in[2];   // (12, 1024)
    float* out = (float*)d_out;                  // 8192*8*1024 v-values + 1 scalar

    dim3 grid(N_COLS / BN, B_SZ / BM);           // (96, 64)
    gemm_kernel<<<grid, 256>>>(x, W, bias);
    routing_kernel<<<B_SZ, 256>>>(out);
    finalize_kernel<<<1, 256>>>(out);
}

// round 4
// speedup vs baseline: 1.3607x; 1.3607x over previous
#include <cuda_runtime.h>
#include <cuda_fp16.h>
#include <cstdint>
#include <cstddef>

#define B_SZ   8192
#define C_SZ   12
#define DIN    1024
#define DOUT   1024
#define N_COLS (C_SZ * DOUT)   // 12288
#define A_SZ   8

// Scratch
__device__ float g_u[(size_t)B_SZ * N_COLS];   // 402 MB
__device__ float g_ent[B_SZ];

// ------------------------------ GEMM (3xFP16 split) ------------------------------
// u[b, co] = sum_i x[b,i] * W[co,i] + bias[co]
// a = ah + al (fp16), b = bh + bl (fp16, W pre-scaled by 32)
// acc += al*bh + ah*bl + ah*bh   (fp32 accumulate) ; u = acc/32 + bias
#define BM 128
#define BN 128
#define BK 32
#define NCHUNK (DIN / BK)      // 32
#define PKH 40                 // padded halves per smem row (80 B, conflict-free frags)
#define PLANE (BM * PKH)       // 5120 halves per plane
#define OFF_AH 0
#define OFF_AL (1 * PLANE)
#define OFF_BH (2 * PLANE)
#define OFF_BL (3 * PLANE)
#define STAGE  (4 * PLANE)     // 20480 halves = 40960 B per stage
#define SMEM_BYTES (2 * STAGE * 2)   // 81920 B

#define W_SCALE     32.0f
#define W_SCALE_INV 0.03125f

__device__ __forceinline__ void split2(float x, float y, uint32_t& hi, uint32_t& lo) {
    const __half hx = __float2half_rn(x);
    const __half hy = __float2half_rn(y);
    const __half lx = __float2half_rn(x - __half2float(hx));
    const __half ly = __float2half_rn(y - __half2float(hy));
    hi = (uint32_t)__half_as_ushort(hx) | ((uint32_t)__half_as_ushort(hy) << 16);
    lo = (uint32_t)__half_as_ushort(lx) | ((uint32_t)__half_as_ushort(ly) << 16);
}

__device__ __forceinline__ void mma_f16(float acc[4], const uint32_t a[4], const uint32_t b[2]) {
    asm volatile(
        "mma.sync.aligned.m16n8k16.row.col.f32.f16.f16.f32 "
        "{%0,%1,%2,%3}, {%4,%5,%6,%7}, {%8,%9}, {%0,%1,%2,%3};\n"
        : "+f"(acc[0]), "+f"(acc[1]), "+f"(acc[2]), "+f"(acc[3])
        : "r"(a[0]), "r"(a[1]), "r"(a[2]), "r"(a[3]), "r"(b[0]), "r"(b[1]));
}

__global__ void __launch_bounds__(512, 1)
gemm_fp16_kernel(const float* __restrict__ X, const float* __restrict__ W,
                 const float* __restrict__ bias)
{
    extern __shared__ __half smh[];

    const int tid  = threadIdx.x;
    const int lane = tid & 31;
    const int warp = tid >> 5;          // 0..15
    const int wm = warp >> 2;           // 0..3  (M: 32 rows each)
    const int wn = warp & 3;            // 0..3  (N: 32 cols each)
    const int bm = blockIdx.y * BM;
    const int bn = blockIdx.x * BN;

    float acc[2][4][4];
    #pragma unroll
    for (int mi = 0; mi < 2; mi++)
        #pragma unroll
        for (int ni = 0; ni < 4; ni++)
            #pragma unroll
            for (int r = 0; r < 4; r++) acc[mi][ni][r] = 0.f;

    // producer mapping: chunk = 128 rows x 32 floats = 1024 float4; 2 per thread
    float4 ra[2], rb[2];
    #pragma unroll
    for (int i = 0; i < 2; i++) {
        const int f = tid + 512 * i;
        const int row = f >> 3, c4 = f & 7;
        ra[i] = *(const float4*)(X + (size_t)(bm + row) * DIN + c4 * 4);
        rb[i] = *(const float4*)(W + (size_t)(bn + row) * DIN + c4 * 4);
    }

    for (int c = 0; c < NCHUNK; ++c) {
        __half* st = smh + (c & 1) * STAGE;

        // split + STS current chunk
        #pragma unroll
        for (int i = 0; i < 2; i++) {
            const int f = tid + 512 * i;
            const int row = f >> 3, c4 = f & 7;
            const int hoff = row * PKH + c4 * 4;
            uint32_t h0, h1, l0, l1;
            split2(ra[i].x, ra[i].y, h0, l0);
            split2(ra[i].z, ra[i].w, h1, l1);
            *(uint2*)(st + OFF_AH + hoff) = make_uint2(h0, h1);
            *(uint2*)(st + OFF_AL + hoff) = make_uint2(l0, l1);
            split2(rb[i].x * W_SCALE, rb[i].y * W_SCALE, h0, l0);
            split2(rb[i].z * W_SCALE, rb[i].w * W_SCALE, h1, l1);
            *(uint2*)(st + OFF_BH + hoff) = make_uint2(h0, h1);
            *(uint2*)(st + OFF_BL + hoff) = make_uint2(l0, l1);
        }
        // prefetch next chunk
        if (c + 1 < NCHUNK) {
            const int k0 = (c + 1) * BK;
            #pragma unroll
            for (int i = 0; i < 2; i++) {
                const int f = tid + 512 * i;
                const int row = f >> 3, c4 = f & 7;
                ra[i] = *(const float4*)(X + (size_t)(bm + row) * DIN + k0 + c4 * 4);
                rb[i] = *(const float4*)(W + (size_t)(bn + row) * DIN + k0 + c4 * 4);
            }
        }
        __syncthreads();

        // compute: 2 k16 steps
        #pragma unroll
        for (int ks = 0; ks < 2; ++ks) {
            const int k0 = ks * 16 + (lane & 3) * 2;

            uint32_t bh[4][2], bl[4][2];
            #pragma unroll
            for (int ni = 0; ni < 4; ni++) {
                const int n0 = wn * 32 + ni * 8 + (lane >> 2);
                bh[ni][0] = *(const uint32_t*)(st + OFF_BH + n0 * PKH + k0);
                bh[ni][1] = *(const uint32_t*)(st + OFF_BH + n0 * PKH + k0 + 8);
                bl[ni][0] = *(const uint32_t*)(st + OFF_BL + n0 * PKH + k0);
                bl[ni][1] = *(const uint32_t*)(st + OFF_BL + n0 * PKH + k0 + 8);
            }
            #pragma unroll
            for (int mi = 0; mi < 2; mi++) {
                const int r0 = wm * 32 + mi * 16 + (lane >> 2);
                uint32_t ah[4], al[4];
                ah[0] = *(const uint32_t*)(st + OFF_AH + r0 * PKH + k0);
                ah[1] = *(const uint32_t*)(st + OFF_AH + (r0 + 8) * PKH + k0);
                ah[2] = *(const uint32_t*)(st + OFF_AH + r0 * PKH + k0 + 8);
                ah[3] = *(const uint32_t*)(st + OFF_AH + (r0 + 8) * PKH + k0 + 8);
                al[0] = *(const uint32_t*)(st + OFF_AL + r0 * PKH + k0);
                al[1] = *(const uint32_t*)(st + OFF_AL + (r0 + 8) * PKH + k0);
                al[2] = *(const uint32_t*)(st + OFF_AL + r0 * PKH + k0 + 8);
                al[3] = *(const uint32_t*)(st + OFF_AL + (r0 + 8) * PKH + k0 + 8);
                #pragma unroll
                for (int ni = 0; ni < 4; ni++) {
                    mma_f16(acc[mi][ni], al, bh[ni]);   // small terms first
                    mma_f16(acc[mi][ni], ah, bl[ni]);
                    mma_f16(acc[mi][ni], ah, bh[ni]);
                }
            }
        }
        __syncthreads();   // safe reuse of this buffer next-next iteration
    }

    // epilogue: u = acc/32 + bias
    #pragma unroll
    for (int mi = 0; mi < 2; mi++) {
        const int row0 = bm + wm * 32 + mi * 16 + (lane >> 2);
        #pragma unroll
        for (int ni = 0; ni < 4; ni++) {
            const int col = bn + wn * 32 + ni * 8 + (lane & 3) * 2;
            const float b0 = __ldg(bias + col), b1 = __ldg(bias + col + 1);
            float* o1 = g_u + (size_t)row0 * N_COLS + col;
            float* o2 = g_u + (size_t)(row0 + 8) * N_COLS + col;
            o1[0] = acc[mi][ni][0] * W_SCALE_INV + b0;
            o1[1] = acc[mi][ni][1] * W_SCALE_INV + b1;
            o2[0] = acc[mi][ni][2] * W_SCALE_INV + b0;
            o2[1] = acc[mi][ni][3] * W_SCALE_INV + b1;
        }
    }
}

// ------------------------------ Routing ------------------------------
__device__ __forceinline__ float warp_sum(float v) {
    #pragma unroll
    for (int o = 16; o; o >>= 1) v += __shfl_xor_sync(0xffffffffu, v, o);
    return v;
}
__device__ __forceinline__ float warp_max(float v) {
    #pragma unroll
    for (int o = 16; o; o >>= 1) v = fmaxf(v, __shfl_xor_sync(0xffffffffu, v, o));
    return v;
}
__device__ __forceinline__ float block_sum(float v, float* red, int lane, int warp) {
    v = warp_sum(v);
    __syncthreads();
    if (lane == 0) red[warp] = v;
    __syncthreads();
    float t = 0.f;
    #pragma unroll
    for (int w = 0; w < 8; w++) t += red[w];
    return t;
}
__device__ __forceinline__ float block_max(float v, float* red, int lane, int warp) {
    v = warp_max(v);
    __syncthreads();
    if (lane == 0) red[warp] = v;
    __syncthreads();
    float t = -3.0e38f;
    #pragma unroll
    for (int w = 0; w < 8; w++) t = fmaxf(t, red[w]);
    return t;
}

// One CTA per batch row b. Routing identical across A=8 -> compute once, replicate.
__global__ void __launch_bounds__(256)
routing_kernel(float* __restrict__ out)
{
    const int b = blockIdx.x;
    const int tid = threadIdx.x;
    const int lane = tid & 31, warp = tid >> 5;
    __shared__ float red[8];
    __shared__ float redc[8][12];

    float u[12][4];
    const float* up = g_u + (size_t)b * N_COLS;
    #pragma unroll
    for (int c = 0; c < 12; c++)
        #pragma unroll
        for (int j = 0; j < 4; j++)
            u[c][j] = up[c * 1024 + tid + 256 * j];

    float blog[12];
    #pragma unroll
    for (int c = 0; c < 12; c++) blog[c] = 0.f;

    float s[4];
    float scale = 0.f;

    #pragma unroll
    for (int it = 0; it < 3; ++it) {
        float mx = blog[0];
        #pragma unroll
        for (int c = 1; c < 12; c++) mx = fmaxf(mx, blog[c]);
        float e[12], se = 0.f;
        #pragma unroll
        for (int c = 0; c < 12; c++) { e[c] = __expf(blog[c] - mx); se += e[c]; }
        const float inv = 1.f / se;

        #pragma unroll
        for (int j = 0; j < 4; j++) {
            float t = 0.f;
            #pragma unroll
            for (int c = 0; c < 12; c++) t += e[c] * u[c][j];
            s[j] = t * inv;
        }

        float n2p = s[0]*s[0] + s[1]*s[1] + s[2]*s[2] + s[3]*s[3];
        const float n2 = block_sum(n2p, red, lane, warp);
        const float n = sqrtf(n2);
        scale = n2 / ((1.f + n2) * (n + 1e-8f));

        if (it < 2) {
            float pd[12];
            #pragma unroll
            for (int c = 0; c < 12; c++) {
                float t = u[c][0]*s[0] + u[c][1]*s[1] + u[c][2]*s[2] + u[c][3]*s[3];
                pd[c] = warp_sum(t);
            }
            if (lane == 0) {
                #pragma unroll
                for (int c = 0; c < 12; c++) redc[warp][c] = pd[c];
            }
            __syncthreads();
            #pragma unroll
            for (int c = 0; c < 12; c++) {
                float t = 0.f;
                #pragma unroll
                for (int w = 0; w < 8; w++) t += redc[w][c];
                blog[c] += scale * t;
            }
            __syncthreads();
        }
    }

    float v0[4];
    #pragma unroll
    for (int j = 0; j < 4; j++) v0[j] = scale * s[j];
    const size_t base = (size_t)b * A_SZ * DOUT;
    #pragma unroll
    for (int a = 0; a < A_SZ; a++)
        #pragma unroll
        for (int j = 0; j < 4; j++)
            out[base + (size_t)a * DOUT + tid + 256 * j] = v0[j];

    // entropy over softmax(s) along D_OUT (reference uses pre-squash s)
    float lm = fmaxf(fmaxf(s[0], s[1]), fmaxf(s[2], s[3]));
    const float gm = block_max(lm, red, lane, warp);
    float ex[4], le = 0.f;
    #pragma unroll
    for (int j = 0; j < 4; j++) { ex[j] = __expf(s[j] - gm); le += ex[j]; }
    const float te = block_sum(le, red, lane, warp);
    const float invd = 1.f / (te + 1e-10f);
    float lp = 0.f;
    #pragma unroll
    for (int j = 0; j < 4; j++) {
        const float p = ex[j] * invd;
        lp += p * __logf(p + 1e-10f);
    }
    const float tp = block_sum(lp, red, lane, warp);
    if (tid == 0) {
        float H = -tp;
        H = fminf(fmaxf(H, 0.f), 10.f);
        g_ent[b] = H;
    }
}

// ------------------------------ Finalize ------------------------------
__global__ void __launch_bounds__(256)
finalize_kernel(float* __restrict__ out)
{
    __shared__ float red[8];
    const int tid = threadIdx.x;
    const int lane = tid & 31, warp = tid >> 5;
    float v = 0.f;
    for (int i = tid; i < B_SZ; i += 256) v += g_ent[i];
    const float s = block_sum(v, red, lane, warp);
    if (tid == 0) {
        const float mean = s / (float)B_SZ;
        const float sig = 1.f / (1.f + expf(-mean));
        out[(size_t)B_SZ * A_SZ * DOUT] = -sig * 0.4f;
    }
}

// ------------------------------ Launch ------------------------------
extern "C" void kernel_launch(void* const* d_in, const int* in_sizes, int n_in,
                              void* d_out, int out_size)
{
    const float* x    = (const float*)d_in[0];
    const float* W    = (const float*)d_in[1];
    const float* bias = (const float*)d_in[2];
    float* out = (float*)d_out;

    static bool configured = false;
    if (!configured) {
        cudaFuncSetAttribute(gemm_fp16_kernel,
                             cudaFuncAttributeMaxDynamicSharedMemorySize, SMEM_BYTES);
        configured = true;
    }
    dim3 grid(N_COLS / BN, B_SZ / BM);           // (96, 64)
    gemm_fp16_kernel<<<grid, 512, SMEM_BYTES>>>(x, W, bias);
    routing_kernel<<<B_SZ, 256>>>(out);
    finalize_kernel<<<1, 256>>>(out);
}

// round 5
// speedup vs baseline: 1.8142x; 1.3333x over previous
#include <cuda_runtime.h>
#include <cuda_fp16.h>
#include <cstdint>
#include <cstddef>

#define B_SZ   8192
#define C_SZ   12
#define DIN    1024
#define DOUT   1024
#define N_COLS (C_SZ * DOUT)   // 12288
#define A_SZ   8

// Scratch (static device allocations allowed)
__device__ float  g_u[(size_t)B_SZ * N_COLS];    // 402 MB
__device__ float  g_ent[B_SZ];
__device__ __half g_xh[(size_t)B_SZ * DIN];      // 16 MB
__device__ __half g_xl[(size_t)B_SZ * DIN];      // 16 MB
__device__ __half g_wh[(size_t)N_COLS * DIN];    // 24 MB (W * 32, hi)
__device__ __half g_wl[(size_t)N_COLS * DIN];    // 24 MB (W * 32, lo)

#define W_SCALE     32.0f
#define W_SCALE_INV 0.03125f

// ------------------------------ split precompute ------------------------------
__device__ __forceinline__ void sp1(float x, __half& h, __half& l) {
    h = __float2half_rn(x);
    l = __float2half_rn(x - __half2float(h));
}

__global__ void __launch_bounds__(256)
split_kernel(const float* __restrict__ src, __half* __restrict__ hi,
             __half* __restrict__ lo, float scale, int n4)
{
    const int i = blockIdx.x * 256 + threadIdx.x;
    if (i >= n4) return;
    const float4 v = *(const float4*)(src + (size_t)i * 4);
    __half h0,h1,h2,h3,l0,l1,l2,l3;
    sp1(v.x * scale, h0, l0); sp1(v.y * scale, h1, l1);
    sp1(v.z * scale, h2, l2); sp1(v.w * scale, h3, l3);
    __half2* hp = (__half2*)(hi + (size_t)i * 4);
    __half2* lp = (__half2*)(lo + (size_t)i * 4);
    hp[0] = __halves2half2(h0, h1); hp[1] = __halves2half2(h2, h3);
    lp[0] = __halves2half2(l0, l1); lp[1] = __halves2half2(l2, l3);
}

// ------------------------------ GEMM ------------------------------
// u[b,co] = (1/32) * sum_i (xh+xl)[b,i]*(wh+wl)[co,i] + bias[co]
// acc += xl*wh + xh*wl + xh*wh   (3x fp16 MMA, fp32 accum)
#define BM 128
#define BN 128
#define BK 32
#define NCHUNK (DIN / BK)       // 32
#define STAGES 4
#define PKH 40                  // halves per smem row (80 B stride)
#define PLANEH (BM * PKH)       // 5120 halves per plane
#define STAGEH (4 * PLANEH)     // AH, AL, BH, BL
#define SMEM_BYTES (STAGES * STAGEH * 2)   // 163840

__device__ __forceinline__ uint32_t s2u(const void* p) {
    return (uint32_t)__cvta_generic_to_shared(p);
}
__device__ __forceinline__ void cp16(const __half* s, const __half* g) {
    asm volatile("cp.async.cg.shared.global [%0], [%1], 16;\n"
                 :: "r"(s2u(s)), "l"(g));
}
__device__ __forceinline__ void ldsm4(uint32_t r[4], const __half* p) {
    asm volatile("ldmatrix.sync.aligned.m8n8.x4.shared.b16 {%0,%1,%2,%3}, [%4];"
                 : "=r"(r[0]), "=r"(r[1]), "=r"(r[2]), "=r"(r[3]) : "r"(s2u(p)));
}
__device__ __forceinline__ void mma_f16(float acc[4], const uint32_t a[4], const uint32_t* b) {
    asm volatile(
        "mma.sync.aligned.m16n8k16.row.col.f32.f16.f16.f32 "
        "{%0,%1,%2,%3}, {%4,%5,%6,%7}, {%8,%9}, {%0,%1,%2,%3};\n"
        : "+f"(acc[0]), "+f"(acc[1]), "+f"(acc[2]), "+f"(acc[3])
        : "r"(a[0]), "r"(a[1]), "r"(a[2]), "r"(a[3]), "r"(b[0]), "r"(b[1]));
}

__global__ void __launch_bounds__(512, 1)
gemm_fp16_kernel(const float* __restrict__ bias)
{
    extern __shared__ __half smh[];

    const int tid  = threadIdx.x;
    const int lane = tid & 31;
    const int warp = tid >> 5;          // 0..15
    const int wm = warp >> 2;           // 0..3 (M: 32 rows each)
    const int wn = warp & 3;            // 0..3 (N: 32 cols each)
    const int bm = blockIdx.y * BM;
    const int bn = blockIdx.x * BN;

    // producer mapping: row = tid>>2 (0..127), 16B chunk c4 = tid&3
    const int prow = tid >> 2;
    const int pc4  = tid & 3;
    const __half* gxh = g_xh + (size_t)(bm + prow) * DIN + pc4 * 8;
    const __half* gxl = g_xl + (size_t)(bm + prow) * DIN + pc4 * 8;
    const __half* gwh = g_wh + (size_t)(bn + prow) * DIN + pc4 * 8;
    const __half* gwl = g_wl + (size_t)(bn + prow) * DIN + pc4 * 8;
    const int soff = prow * PKH + pc4 * 8;

    float acc[2][4][4];
    #pragma unroll
    for (int mi = 0; mi < 2; mi++)
        #pragma unroll
        for (int ni = 0; ni < 4; ni++)
            #pragma unroll
            for (int r = 0; r < 4; r++) acc[mi][ni][r] = 0.f;

    // prologue: stages 0..2
    #pragma unroll
    for (int c = 0; c < STAGES - 1; ++c) {
        __half* st = smh + (c & (STAGES - 1)) * STAGEH;
        cp16(st + soff,              gxh + c * BK);
        cp16(st + PLANEH + soff,     gxl + c * BK);
        cp16(st + 2 * PLANEH + soff, gwh + c * BK);
        cp16(st + 3 * PLANEH + soff, gwl + c * BK);
        asm volatile("cp.async.commit_group;\n");
    }

    // fragment base addresses (per warp, per plane)
    const int arow = (lane & 15);
    const int acol = (lane >> 4) * 8;
    const int brow = (lane & 7) + ((lane >> 4) << 3);
    const int bcol = ((lane >> 3) & 1) * 8;

    for (int c = 0; c < NCHUNK; ++c) {
        asm volatile("cp.async.wait_group 2;\n" ::: "memory");
        __syncthreads();

        // issue stage c+3
        if (c + STAGES - 1 < NCHUNK) {
            const int cn = c + STAGES - 1;
            __half* st = smh + (cn & (STAGES - 1)) * STAGEH;
            cp16(st + soff,              gxh + cn * BK);
            cp16(st + PLANEH + soff,     gxl + cn * BK);
            cp16(st + 2 * PLANEH + soff, gwh + cn * BK);
            cp16(st + 3 * PLANEH + soff, gwl + cn * BK);
        }
        asm volatile("cp.async.commit_group;\n");

        // consume stage c
        const __half* st = smh + (c & (STAGES - 1)) * STAGEH;
        #pragma unroll
        for (int ks = 0; ks < 2; ++ks) {
            const int kh = ks * 16;
            uint32_t ah[2][4], al[2][4];
            #pragma unroll
            for (int mi = 0; mi < 2; mi++) {
                const int r0 = wm * 32 + mi * 16;
                ldsm4(ah[mi], st + (r0 + arow) * PKH + kh + acol);
                ldsm4(al[mi], st + PLANEH + (r0 + arow) * PKH + kh + acol);
            }
            uint32_t bh[2][4], bl[2][4];   // [nip][4] = {b0,b1 ni_even, b0,b1 ni_odd}
            #pragma unroll
            for (int nip = 0; nip < 2; nip++) {
                const int n0 = wn * 32 + nip * 16;
                ldsm4(bh[nip], st + 2 * PLANEH + (n0 + brow) * PKH + kh + bcol);
                ldsm4(bl[nip], st + 3 * PLANEH + (n0 + brow) * PKH + kh + bcol);
            }
            #pragma unroll
            for (int mi = 0; mi < 2; mi++)
                #pragma unroll
                for (int ni = 0; ni < 4; ni++) {
                    const uint32_t* pbh = &bh[ni >> 1][(ni & 1) * 2];
                    const uint32_t* pbl = &bl[ni >> 1][(ni & 1) * 2];
                    mma_f16(acc[mi][ni], al[mi], pbh);   // small terms first
                    mma_f16(acc[mi][ni], ah[mi], pbl);
                    mma_f16(acc[mi][ni], ah[mi], pbh);
                }
        }
    }

    // epilogue: u = acc/32 + bias
    #pragma unroll
    for (int mi = 0; mi < 2; mi++) {
        const int row0 = bm + wm * 32 + mi * 16 + (lane >> 2);
        #pragma unroll
        for (int ni = 0; ni < 4; ni++) {
            const int col = bn + wn * 32 + ni * 8 + (lane & 3) * 2;
            const float b0 = __ldg(bias + col), b1 = __ldg(bias + col + 1);
            float* o1 = g_u + (size_t)row0 * N_COLS + col;
            float* o2 = g_u + (size_t)(row0 + 8) * N_COLS + col;
            o1[0] = acc[mi][ni][0] * W_SCALE_INV + b0;
            o1[1] = acc[mi][ni][1] * W_SCALE_INV + b1;
            o2[0] = acc[mi][ni][2] * W_SCALE_INV + b0;
            o2[1] = acc[mi][ni][3] * W_SCALE_INV + b1;
        }
    }
}

// ------------------------------ Routing ------------------------------
__device__ __forceinline__ float warp_sum(float v) {
    #pragma unroll
    for (int o = 16; o; o >>= 1) v += __shfl_xor_sync(0xffffffffu, v, o);
    return v;
}
__device__ __forceinline__ float warp_max(float v) {
    #pragma unroll
    for (int o = 16; o; o >>= 1) v = fmaxf(v, __shfl_xor_sync(0xffffffffu, v, o));
    return v;
}
__device__ __forceinline__ float block_sum(float v, float* red, int lane, int warp) {
    v = warp_sum(v);
    __syncthreads();
    if (lane == 0) red[warp] = v;
    __syncthreads();
    float t = 0.f;
    #pragma unroll
    for (int w = 0; w < 8; w++) t += red[w];
    return t;
}
__device__ __forceinline__ float block_max(float v, float* red, int lane, int warp) {
    v = warp_max(v);
    __syncthreads();
    if (lane == 0) red[warp] = v;
    __syncthreads();
    float t = -3.0e38f;
    #pragma unroll
    for (int w = 0; w < 8; w++) t = fmaxf(t, red[w]);
    return t;
}

// One CTA per batch row b. Routing identical across A=8 -> compute once, replicate.
__global__ void __launch_bounds__(256)
routing_kernel(float* __restrict__ out)
{
    const int b = blockIdx.x;
    const int tid = threadIdx.x;
    const int lane = tid & 31, warp = tid >> 5;
    __shared__ float red[8];
    __shared__ float redc[8][12];

    float u[12][4];
    const float* up = g_u + (size_t)b * N_COLS;
    #pragma unroll
    for (int c = 0; c < 12; c++)
        #pragma unroll
        for (int j = 0; j < 4; j++)
            u[c][j] = up[c * 1024 + tid + 256 * j];

    float blog[12];
    #pragma unroll
    for (int c = 0; c < 12; c++) blog[c] = 0.f;

    float s[4];
    float scale = 0.f;

    #pragma unroll
    for (int it = 0; it < 3; ++it) {
        float mx = blog[0];
        #pragma unroll
        for (int c = 1; c < 12; c++) mx = fmaxf(mx, blog[c]);
        float e[12], se = 0.f;
        #pragma unroll
        for (int c = 0; c < 12; c++) { e[c] = __expf(blog[c] - mx); se += e[c]; }
        const float inv = 1.f / se;

        #pragma unroll
        for (int j = 0; j < 4; j++) {
            float t = 0.f;
            #pragma unroll
            for (int c = 0; c < 12; c++) t += e[c] * u[c][j];
            s[j] = t * inv;
        }

        float n2p = s[0]*s[0] + s[1]*s[1] + s[2]*s[2] + s[3]*s[3];
        const float n2 = block_sum(n2p, red, lane, warp);
        const float n = sqrtf(n2);
        scale = n2 / ((1.f + n2) * (n + 1e-8f));

        if (it < 2) {
            float pd[12];
            #pragma unroll
            for (int c = 0; c < 12; c++) {
                float t = u[c][0]*s[0] + u[c][1]*s[1] + u[c][2]*s[2] + u[c][3]*s[3];
                pd[c] = warp_sum(t);
            }
            if (lane == 0) {
                #pragma unroll
                for (int c = 0; c < 12; c++) redc[warp][c] = pd[c];
            }
            __syncthreads();
            #pragma unroll
            for (int c = 0; c < 12; c++) {
                float t = 0.f;
                #pragma unroll
                for (int w = 0; w < 8; w++) t += redc[w][c];
                blog[c] += scale * t;
            }
            __syncthreads();
        }
    }

    float v0[4];
    #pragma unroll
    for (int j = 0; j < 4; j++) v0[j] = scale * s[j];
    const size_t base = (size_t)b * A_SZ * DOUT;
    #pragma unroll
    for (int a = 0; a < A_SZ; a++)
        #pragma unroll
        for (int j = 0; j < 4; j++)
            out[base + (size_t)a * DOUT + tid + 256 * j] = v0[j];

    // entropy over softmax(s) along D_OUT (reference uses pre-squash s)
    float lm = fmaxf(fmaxf(s[0], s[1]), fmaxf(s[2], s[3]));
    const float gm = block_max(lm, red, lane, warp);
    float ex[4], le = 0.f;
    #pragma unroll
    for (int j = 0; j < 4; j++) { ex[j] = __expf(s[j] - gm); le += ex[j]; }
    const float te = block_sum(le, red, lane, warp);
    const float invd = 1.f / (te + 1e-10f);
    float lp = 0.f;
    #pragma unroll
    for (int j = 0; j < 4; j++) {
        const float p = ex[j] * invd;
        lp += p * __logf(p + 1e-10f);
    }
    const float tp = block_sum(lp, red, lane, warp);
    if (tid == 0) {
        float H = -tp;
        H = fminf(fmaxf(H, 0.f), 10.f);
        g_ent[b] = H;
    }
}

// ------------------------------ Finalize ------------------------------
__global__ void __launch_bounds__(256)
finalize_kernel(float* __restrict__ out)
{
    __shared__ float red[8];
    const int tid = threadIdx.x;
    const int lane = tid & 31, warp = tid >> 5;
    float v = 0.f;
    for (int i = tid; i < B_SZ; i += 256) v += g_ent[i];
    const float s = block_sum(v, red, lane, warp);
    if (tid == 0) {
        const float mean = s / (float)B_SZ;
        const float sig = 1.f / (1.f + expf(-mean));
        out[(size_t)B_SZ * A_SZ * DOUT] = -sig * 0.4f;
    }
}

// ------------------------------ Launch ------------------------------
extern "C" void kernel_launch(void* const* d_in, const int* in_sizes, int n_in,
                              void* d_out, int out_size)
{
    const float* x    = (const float*)d_in[0];
    const float* W    = (const float*)d_in[1];
    const float* bias = (const float*)d_in[2];
    float* out = (float*)d_out;

    cudaFuncSetAttribute(gemm_fp16_kernel,
                         cudaFuncAttributeMaxDynamicSharedMemorySize, SMEM_BYTES);

    // split X and W into fp16 hi/lo planes (W scaled by 32)
    {
        __half *xh, *xl, *wh, *wl;
        cudaGetSymbolAddress((void**)&xh, g_xh);
        cudaGetSymbolAddress((void**)&xl, g_xl);
        cudaGetSymbolAddress((void**)&wh, g_wh);
        cudaGetSymbolAddress((void**)&wl, g_wl);
        const int nx4 = B_SZ * DIN / 4;       // 2M
        const int nw4 = N_COLS * DIN / 4;     // ~3.1M
        split_kernel<<<(nx4 + 255) / 256, 256>>>(x, xh, xl, 1.0f, nx4);
        split_kernel<<<(nw4 + 255) / 256, 256>>>(W, wh, wl, W_SCALE, nw4);
    }

    dim3 grid(N_COLS / BN, B_SZ / BM);        // (96, 64)
    gemm_fp16_kernel<<<grid, 512, SMEM_BYTES>>>(bias);
    routing_kernel<<<B_SZ, 256>>>(out);
    finalize_kernel<<<1, 256>>>(out);
}

// round 6
// speedup vs baseline: 2.0149x; 1.1106x over previous
#include <cuda_runtime.h>
#include <cuda_fp16.h>
#include <cstdint>
#include <cstddef>

#define B_SZ   8192
#define C_SZ   12
#define DIN    1024
#define DOUT   1024
#define N_COLS (C_SZ * DOUT)   // 12288
#define A_SZ   8

// Scratch (static device allocations allowed)
__device__ float  g_u[(size_t)B_SZ * N_COLS];    // 402 MB
__device__ float  g_ent[B_SZ];
__device__ __half g_xh[(size_t)B_SZ * DIN];
__device__ __half g_xl[(size_t)B_SZ * DIN];
__device__ __half g_wh[(size_t)N_COLS * DIN];    // W * 32, hi
__device__ __half g_wl[(size_t)N_COLS * DIN];    // W * 32, lo

#define W_SCALE     32.0f
#define W_SCALE_INV 0.03125f

// ------------------------------ split precompute ------------------------------
__device__ __forceinline__ void sp1(float x, __half& h, __half& l) {
    h = __float2half_rn(x);
    l = __float2half_rn(x - __half2float(h));
}

__global__ void __launch_bounds__(256)
split_kernel(const float* __restrict__ src, __half* __restrict__ hi,
             __half* __restrict__ lo, float scale, int n4)
{
    const int i = blockIdx.x * 256 + threadIdx.x;
    if (i >= n4) return;
    const float4 v = *(const float4*)(src + (size_t)i * 4);
    __half h0,h1,h2,h3,l0,l1,l2,l3;
    sp1(v.x * scale, h0, l0); sp1(v.y * scale, h1, l1);
    sp1(v.z * scale, h2, l2); sp1(v.w * scale, h3, l3);
    __half2* hp = (__half2*)(hi + (size_t)i * 4);
    __half2* lp = (__half2*)(lo + (size_t)i * 4);
    hp[0] = __halves2half2(h0, h1); hp[1] = __halves2half2(h2, h3);
    lp[0] = __halves2half2(l0, l1); lp[1] = __halves2half2(l2, l3);
}

// ------------------------------ GEMM ------------------------------
// u[b,co] = (1/32) * sum_i (xh+xl)[b,i]*(wh+wl)[co,i] + bias[co]
// acc += xl*wh + xh*wl + xh*wh   (3x fp16 MMA, fp32 accum)
// 256 threads, 8 warps: 2(M) x 4(N), warp tile 64x32. BK=64, 3-stage cp.async.
#define BM 128
#define BN 128
#define BK 64
#define NCHUNK (DIN / BK)       // 16
#define STAGES 3
#define PKH 72                  // halves per smem row (144 B stride, conflict-free)
#define PLANEH (BM * PKH)       // 9216 halves
#define STAGEH (4 * PLANEH)     // AH, AL, BH, BL
#define SMEM_BYTES (STAGES * STAGEH * 2)   // 221184

__device__ __forceinline__ uint32_t s2u(const void* p) {
    return (uint32_t)__cvta_generic_to_shared(p);
}
__device__ __forceinline__ void cp16(const __half* s, const __half* g) {
    asm volatile("cp.async.cg.shared.global [%0], [%1], 16;\n"
                 :: "r"(s2u(s)), "l"(g));
}
__device__ __forceinline__ void ldsm4(uint32_t r[4], const __half* p) {
    asm volatile("ldmatrix.sync.aligned.m8n8.x4.shared.b16 {%0,%1,%2,%3}, [%4];"
                 : "=r"(r[0]), "=r"(r[1]), "=r"(r[2]), "=r"(r[3]) : "r"(s2u(p)));
}
__device__ __forceinline__ void mma_f16(float acc[4], const uint32_t a[4], const uint32_t* b) {
    asm volatile(
        "mma.sync.aligned.m16n8k16.row.col.f32.f16.f16.f32 "
        "{%0,%1,%2,%3}, {%4,%5,%6,%7}, {%8,%9}, {%0,%1,%2,%3};\n"
        : "+f"(acc[0]), "+f"(acc[1]), "+f"(acc[2]), "+f"(acc[3])
        : "r"(a[0]), "r"(a[1]), "r"(a[2]), "r"(a[3]), "r"(b[0]), "r"(b[1]));
}

__global__ void __launch_bounds__(256, 1)
gemm_fp16_kernel(const float* __restrict__ bias)
{
    extern __shared__ __half smh[];

    const int tid  = threadIdx.x;
    const int lane = tid & 31;
    const int warp = tid >> 5;          // 0..7
    const int wm = warp >> 2;           // 0..1 (M: 64 rows each)
    const int wn = warp & 3;            // 0..3 (N: 32 cols each)
    const int bm = blockIdx.y * BM;
    const int bn = blockIdx.x * BN;

    // producer mapping: 4 iters cover 128 rows x 8 16B-chunks per plane
    int soff[4];
    size_t xoff[4], woff[4];
    #pragma unroll
    for (int i = 0; i < 4; i++) {
        const int f = tid + 256 * i;
        const int row = f >> 3, c4 = f & 7;
        soff[i] = row * PKH + c4 * 8;
        xoff[i] = (size_t)(bm + row) * DIN + c4 * 8;
        woff[i] = (size_t)(bn + row) * DIN + c4 * 8;
    }

    float acc[4][4][4];
    #pragma unroll
    for (int mi = 0; mi < 4; mi++)
        #pragma unroll
        for (int ni = 0; ni < 4; ni++)
            #pragma unroll
            for (int r = 0; r < 4; r++) acc[mi][ni][r] = 0.f;

    // prologue: stages for chunks 0,1
    #pragma unroll
    for (int c = 0; c < STAGES - 1; ++c) {
        __half* st = smh + c * STAGEH;
        #pragma unroll
        for (int i = 0; i < 4; i++) {
            cp16(st + soff[i],              g_xh + xoff[i] + c * BK);
            cp16(st + PLANEH + soff[i],     g_xl + xoff[i] + c * BK);
            cp16(st + 2 * PLANEH + soff[i], g_wh + woff[i] + c * BK);
            cp16(st + 3 * PLANEH + soff[i], g_wl + woff[i] + c * BK);
        }
        asm volatile("cp.async.commit_group;\n");
    }

    const int arow = (lane & 15);
    const int acol = (lane >> 4) * 8;
    const int brow = (lane & 7) + ((lane >> 4) << 3);
    const int bcol = ((lane >> 3) & 1) * 8;

    int sb_c = 0;                         // stage of chunk c
    for (int c = 0; c < NCHUNK; ++c) {
        asm volatile("cp.async.wait_group 1;\n" ::: "memory");
        __syncthreads();

        // issue chunk c+2
        if (c + STAGES - 1 < NCHUNK) {
            const int cn = c + STAGES - 1;
            int sbn = sb_c + STAGES - 1; if (sbn >= STAGES) sbn -= STAGES;
            __half* st = smh + sbn * STAGEH;
            #pragma unroll
            for (int i = 0; i < 4; i++) {
                cp16(st + soff[i],              g_xh + xoff[i] + cn * BK);
                cp16(st + PLANEH + soff[i],     g_xl + xoff[i] + cn * BK);
                cp16(st + 2 * PLANEH + soff[i], g_wh + woff[i] + cn * BK);
                cp16(st + 3 * PLANEH + soff[i], g_wl + woff[i] + cn * BK);
            }
        }
        asm volatile("cp.async.commit_group;\n");

        // consume chunk c: 4 k16-steps
        const __half* st = smh + sb_c * STAGEH;
        #pragma unroll
        for (int ks = 0; ks < 4; ++ks) {
            const int kh = ks * 16;
            uint32_t ah[4][4], al[4][4];
            #pragma unroll
            for (int mi = 0; mi < 4; mi++) {
                const int r0 = wm * 64 + mi * 16;
                ldsm4(ah[mi], st + (r0 + arow) * PKH + kh + acol);
                ldsm4(al[mi], st + PLANEH + (r0 + arow) * PKH + kh + acol);
            }
            uint32_t bh[2][4], bl[2][4];
            #pragma unroll
            for (int nip = 0; nip < 2; nip++) {
                const int n0 = wn * 32 + nip * 16;
                ldsm4(bh[nip], st + 2 * PLANEH + (n0 + brow) * PKH + kh + bcol);
                ldsm4(bl[nip], st + 3 * PLANEH + (n0 + brow) * PKH + kh + bcol);
            }
            #pragma unroll
            for (int mi = 0; mi < 4; mi++)
                #pragma unroll
                for (int ni = 0; ni < 4; ni++) {
                    const uint32_t* pbh = &bh[ni >> 1][(ni & 1) * 2];
                    const uint32_t* pbl = &bl[ni >> 1][(ni & 1) * 2];
                    mma_f16(acc[mi][ni], al[mi], pbh);   // small terms first
                    mma_f16(acc[mi][ni], ah[mi], pbl);
                    mma_f16(acc[mi][ni], ah[mi], pbh);
                }
        }
        if (++sb_c == STAGES) sb_c = 0;
    }

    // epilogue: u = acc/32 + bias
    #pragma unroll
    for (int mi = 0; mi < 4; mi++) {
        const int row0 = bm + wm * 64 + mi * 16 + (lane >> 2);
        #pragma unroll
        for (int ni = 0; ni < 4; ni++) {
            const int col = bn + wn * 32 + ni * 8 + (lane & 3) * 2;
            const float b0 = __ldg(bias + col), b1 = __ldg(bias + col + 1);
            float* o1 = g_u + (size_t)row0 * N_COLS + col;
            float* o2 = g_u + (size_t)(row0 + 8) * N_COLS + col;
            o1[0] = acc[mi][ni][0] * W_SCALE_INV + b0;
            o1[1] = acc[mi][ni][1] * W_SCALE_INV + b1;
            o2[0] = acc[mi][ni][2] * W_SCALE_INV + b0;
            o2[1] = acc[mi][ni][3] * W_SCALE_INV + b1;
        }
    }
}

// ------------------------------ Routing ------------------------------
__device__ __forceinline__ float warp_sum(float v) {
    #pragma unroll
    for (int o = 16; o; o >>= 1) v += __shfl_xor_sync(0xffffffffu, v, o);
    return v;
}
__device__ __forceinline__ float warp_max(float v) {
    #pragma unroll
    for (int o = 16; o; o >>= 1) v = fmaxf(v, __shfl_xor_sync(0xffffffffu, v, o));
    return v;
}
__device__ __forceinline__ float block_sum(float v, float* red, int lane, int warp) {
    v = warp_sum(v);
    __syncthreads();
    if (lane == 0) red[warp] = v;
    __syncthreads();
    float t = 0.f;
    #pragma unroll
    for (int w = 0; w < 8; w++) t += red[w];
    return t;
}
__device__ __forceinline__ float block_max(float v, float* red, int lane, int warp) {
    v = warp_max(v);
    __syncthreads();
    if (lane == 0) red[warp] = v;
    __syncthreads();
    float t = -3.0e38f;
    #pragma unroll
    for (int w = 0; w < 8; w++) t = fmaxf(t, red[w]);
    return t;
}

// One CTA per batch row b. Routing identical across A=8 -> compute once, replicate.
__global__ void __launch_bounds__(256)
routing_kernel(float* __restrict__ out)
{
    const int b = blockIdx.x;
    const int tid = threadIdx.x;
    const int lane = tid & 31, warp = tid >> 5;
    __shared__ float red[8];
    __shared__ float redc[8][12];
    __shared__ float sv[1024];

    float u[12][4];
    const float* up = g_u + (size_t)b * N_COLS;
    #pragma unroll
    for (int c = 0; c < 12; c++)
        #pragma unroll
        for (int j = 0; j < 4; j++)
            u[c][j] = up[c * 1024 + tid + 256 * j];

    float blog[12];
    #pragma unroll
    for (int c = 0; c < 12; c++) blog[c] = 0.f;

    float s[4];
    float scale = 0.f;

    #pragma unroll
    for (int it = 0; it < 3; ++it) {
        float mx = blog[0];
        #pragma unroll
        for (int c = 1; c < 12; c++) mx = fmaxf(mx, blog[c]);
        float e[12], se = 0.f;
        #pragma unroll
        for (int c = 0; c < 12; c++) { e[c] = __expf(blog[c] - mx); se += e[c]; }
        const float inv = 1.f / se;

        #pragma unroll
        for (int j = 0; j < 4; j++) {
            float t = 0.f;
            #pragma unroll
            for (int c = 0; c < 12; c++) t += e[c] * u[c][j];
            s[j] = t * inv;
        }

        float n2p = s[0]*s[0] + s[1]*s[1] + s[2]*s[2] + s[3]*s[3];
        const float n2 = block_sum(n2p, red, lane, warp);
        const float n = sqrtf(n2);
        scale = n2 / ((1.f + n2) * (n + 1e-8f));

        if (it < 2) {
            float pd[12];
            #pragma unroll
            for (int c = 0; c < 12; c++) {
                float t = u[c][0]*s[0] + u[c][1]*s[1] + u[c][2]*s[2] + u[c][3]*s[3];
                pd[c] = warp_sum(t);
            }
            if (lane == 0) {
                #pragma unroll
                for (int c = 0; c < 12; c++) redc[warp][c] = pd[c];
            }
            __syncthreads();
            #pragma unroll
            for (int c = 0; c < 12; c++) {
                float t = 0.f;
                #pragma unroll
                for (int w = 0; w < 8; w++) t += redc[w][c];
                blog[c] += scale * t;
            }
            __syncthreads();
        }
    }

    // stage v in smem, then coalesced float4 stores for all 8 A-copies
    #pragma unroll
    for (int j = 0; j < 4; j++) sv[tid + 256 * j] = scale * s[j];
    __syncthreads();
    {
        const float4* sv4 = (const float4*)sv;
        const size_t base = (size_t)b * A_SZ * DOUT;
        #pragma unroll
        for (int i = 0; i < 8; i++) {
            const int idx = tid + 256 * i;          // 0..2047
            const int a = idx >> 8, q = idx & 255;
            *(float4*)(out + base + (size_t)a * DOUT + q * 4) = sv4[q];
        }
    }

    // entropy over softmax(s) along D_OUT (reference uses pre-squash s)
    float lm = fmaxf(fmaxf(s[0], s[1]), fmaxf(s[2], s[3]));
    const float gm = block_max(lm, red, lane, warp);
    float ex[4], le = 0.f;
    #pragma unroll
    for (int j = 0; j < 4; j++) { ex[j] = __expf(s[j] - gm); le += ex[j]; }
    const float te = block_sum(le, red, lane, warp);
    const float invd = 1.f / (te + 1e-10f);
    float lp = 0.f;
    #pragma unroll
    for (int j = 0; j < 4; j++) {
        const float p = ex[j] * invd;
        lp += p * __logf(p + 1e-10f);
    }
    const float tp = block_sum(lp, red, lane, warp);
    if (tid == 0) {
        float H = -tp;
        H = fminf(fmaxf(H, 0.f), 10.f);
        g_ent[b] = H;
    }
}

// ------------------------------ Finalize ------------------------------
__global__ void __launch_bounds__(256)
finalize_kernel(float* __restrict__ out)
{
    __shared__ float red[8];
    const int tid = threadIdx.x;
    const int lane = tid & 31, warp = tid >> 5;
    float v = 0.f;
    for (int i = tid; i < B_SZ; i += 256) v += g_ent[i];
    const float s = block_sum(v, red, lane, warp);
    if (tid == 0) {
        const float mean = s / (float)B_SZ;
        const float sig = 1.f / (1.f + expf(-mean));
        out[(size_t)B_SZ * A_SZ * DOUT] = -sig * 0.4f;
    }
}

// ------------------------------ Launch ------------------------------
extern "C" void kernel_launch(void* const* d_in, const int* in_sizes, int n_in,
                              void* d_out, int out_size)
{
    const float* x    = (const float*)d_in[0];
    const float* W    = (const float*)d_in[1];
    const float* bias = (const float*)d_in[2];
    float* out = (float*)d_out;

    cudaFuncSetAttribute(gemm_fp16_kernel,
                         cudaFuncAttributeMaxDynamicSharedMemorySize, SMEM_BYTES);

    // split X and W into fp16 hi/lo planes (W scaled by 32)
    {
        __half *xh, *xl, *wh, *wl;
        cudaGetSymbolAddress((void**)&xh, g_xh);
        cudaGetSymbolAddress((void**)&xl, g_xl);
        cudaGetSymbolAddress((void**)&wh, g_wh);
        cudaGetSymbolAddress((void**)&wl, g_wl);
        const int nx4 = B_SZ * DIN / 4;
        const int nw4 = N_COLS * DIN / 4;
        split_kernel<<<(nx4 + 255) / 256, 256>>>(x, xh, xl, 1.0f, nx4);
        split_kernel<<<(nw4 + 255) / 256, 256>>>(W, wh, wl, W_SCALE, nw4);
    }

    dim3 grid(N_COLS / BN, B_SZ / BM);        // (96, 64)
    gemm_fp16_kernel<<<grid, 256, SMEM_BYTES>>>(bias);
    routing_kernel<<<B_SZ, 256>>>(out);
    finalize_kernel<<<1, 256>>>(out);
}